// round 1
// baseline (speedup 1.0000x reference)
#include <cuda_runtime.h>

#define BATCH    8192
#define HID      128
#define GATES    512
#define LOOKBACK 48
#define HORIZON  12
#define TSTEPS   60
#define DIN      8
#define STATE    (BATCH*HID)

// ---------------- scratch (device globals; no allocations) ----------------
__device__ float g_Wx0[DIN*GATES];   // packed [k][col], col = unit*4+gate
__device__ float g_Wh0[HID*GATES];
__device__ float g_b0 [GATES];
__device__ float g_Wx1[HID*GATES];
__device__ float g_Wh1[HID*GATES];
__device__ float g_b1 [GATES];
__device__ float g_h0 [2*STATE];     // ping-pong h buffers per layer
__device__ float g_h1 [2*STATE];
__device__ float g_c0 [STATE];
__device__ float g_c1 [STATE];
__device__ float g_pred[BATCH];

// ---------------- weight repack + state zero ----------------
// packed col p = j*4 + g  (j = hidden unit, g = 0:i 1:f 2:g 3:o)
// original gate-major row = g*128 + j
__global__ void prep_kernel(const float* __restrict__ Wih0, const float* __restrict__ Whh0,
                            const float* __restrict__ bih0, const float* __restrict__ bhh0,
                            const float* __restrict__ Wih1, const float* __restrict__ Whh1,
                            const float* __restrict__ bih1, const float* __restrict__ bhh1)
{
    const int N_WX0 = DIN*GATES;
    const int N_WH  = HID*GATES;
    const int total = N_WX0 + 3*N_WH + 2*GATES + 4*STATE;
    for (int idx = blockIdx.x*blockDim.x + threadIdx.x; idx < total;
         idx += gridDim.x*blockDim.x) {
        int i = idx;
        if (i < N_WX0) { int k=i>>9, p=i&511; int row=(p&3)*HID+(p>>2);
                         g_Wx0[i] = Wih0[row*DIN + k]; continue; }
        i -= N_WX0;
        if (i < N_WH)  { int k=i>>9, p=i&511; int row=(p&3)*HID+(p>>2);
                         g_Wh0[i] = Whh0[row*HID + k]; continue; }
        i -= N_WH;
        if (i < N_WH)  { int k=i>>9, p=i&511; int row=(p&3)*HID+(p>>2);
                         g_Wx1[i] = Wih1[row*HID + k]; continue; }
        i -= N_WH;
        if (i < N_WH)  { int k=i>>9, p=i&511; int row=(p&3)*HID+(p>>2);
                         g_Wh1[i] = Whh1[row*HID + k]; continue; }
        i -= N_WH;
        if (i < GATES) { int row=(i&3)*HID+(i>>2); g_b0[i]=bih0[row]+bhh0[row]; continue; }
        i -= GATES;
        if (i < GATES) { int row=(i&3)*HID+(i>>2); g_b1[i]=bih1[row]+bhh1[row]; continue; }
        i -= GATES;
        if (i < STATE) { g_h0[i] = 0.f; continue; }  // ping buffer 0 only
        i -= STATE;
        if (i < STATE) { g_h1[i] = 0.f; continue; }
        i -= STATE;
        if (i < STATE) { g_c0[i] = 0.f; continue; }
        i -= STATE;
        g_c1[i] = 0.f;
    }
}

// ---------------- fast activations (fp32-exact enough: __expf rel err ~2^-21) ----
__device__ __forceinline__ float sigm_f(float x){
    x = fminf(fmaxf(x, -30.f), 30.f);
    return __fdividef(1.f, 1.f + __expf(-x));
}
__device__ __forceinline__ float tanh_f(float x){
    x = fminf(fmaxf(x, -15.f), 15.f);
    float e = __expf(2.f*x);
    return 1.f - __fdividef(2.f, e + 1.f);
}

// packed f32x2 FMA (Blackwell-only PTX; ptxas never auto-fuses this)
#define PACK2(d,x,y)  asm("mov.b64 %0, {%1, %2};" : "=l"(d) : "f"(x), "f"(y))
#define UNPACK2(x,y,s) asm("mov.b64 {%0, %1}, %2;" : "=f"(x), "=f"(y) : "l"(s))
#define FMA2(d,a,b)   asm("fma.rn.f32x2 %0, %1, %2, %0;" : "+l"(d) : "l"(a), "l"(b))

// ---------------- fused LSTM cell ----------------
// gates = [x , h_prev] @ [Wx ; Wh] + b  ; then pointwise update, no gate scratch.
// Tile: 128 rows x 128 packed cols (= 32 complete hidden units) per block.
__global__ __launch_bounds__(256) void lstm_cell(
    const float* __restrict__ xsrc, int sx, int Kx,
    const float* __restrict__ Wx, const float* __restrict__ Wh,
    const float* __restrict__ bias, const float* __restrict__ hprev,
    float* __restrict__ cbuf, float* __restrict__ hout,
    const float* __restrict__ bg, int use_bg)
{
    __shared__ float As[8][132];
    __shared__ float Bs[8][132];
    const int tid = threadIdx.x;
    const int tx  = tid & 15, ty = tid >> 4;
    const int m0  = blockIdx.x * 128;
    const int n0  = blockIdx.y * 128;

    unsigned long long acc[8][4];
    #pragma unroll
    for (int r = 0; r < 8; r++)
        #pragma unroll
        for (int i = 0; i < 4; i++) acc[r][i] = 0ULL;

    const int Ktot = Kx + HID;
    for (int k0 = 0; k0 < Ktot; k0 += 8) {
        #pragma unroll
        for (int i = 0; i < 4; i++) {                 // A tile: 128 rows x 8 k
            int idx = tid + i*256;
            int m = idx >> 3, kk = idx & 7;
            int k = k0 + kk;
            float v;
            if (k < Kx) {
                v = (use_bg && k == 0) ? bg[m0+m] : xsrc[(m0+m)*sx + k];
            } else {
                v = hprev[(m0+m)*HID + (k - Kx)];
            }
            As[kk][m] = v;
        }
        #pragma unroll
        for (int i = 0; i < 4; i++) {                 // B tile: 8 k x 128 cols
            int idx = tid + i*256;
            int col = idx & 127, kk = idx >> 7;
            int k = k0 + kk;
            Bs[kk][col] = (k < Kx) ? Wx[k*GATES + n0 + col]
                                   : Wh[(k-Kx)*GATES + n0 + col];
        }
        __syncthreads();
        #pragma unroll
        for (int kk = 0; kk < 8; kk++) {
            float4 b0 = *(const float4*)&Bs[kk][tx*8];
            float4 b1 = *(const float4*)&Bs[kk][tx*8+4];
            unsigned long long bp0, bp1, bp2, bp3;
            PACK2(bp0, b0.x, b0.y); PACK2(bp1, b0.z, b0.w);
            PACK2(bp2, b1.x, b1.y); PACK2(bp3, b1.z, b1.w);
            float4 a0 = *(const float4*)&As[kk][ty*8];
            float4 a1 = *(const float4*)&As[kk][ty*8+4];
            float ar[8] = {a0.x,a0.y,a0.z,a0.w,a1.x,a1.y,a1.z,a1.w};
            #pragma unroll
            for (int r = 0; r < 8; r++) {
                unsigned long long ap; PACK2(ap, ar[r], ar[r]);
                FMA2(acc[r][0], ap, bp0);
                FMA2(acc[r][1], ap, bp1);
                FMA2(acc[r][2], ap, bp2);
                FMA2(acc[r][3], ap, bp3);
            }
        }
        __syncthreads();
    }

    // ---- epilogue: bias + gates + state update (this block owns these units) ----
    const int cbase = n0 + tx*8;
    float bb[8];
    #pragma unroll
    for (int i = 0; i < 8; i++) bb[i] = bias[cbase + i];
    const int u0 = cbase >> 2;
    #pragma unroll
    for (int r = 0; r < 8; r++) {
        int m = m0 + ty*8 + r;
        float gi0,gf0,gg0,go0, gi1,gf1,gg1,go1;
        UNPACK2(gi0, gf0, acc[r][0]); UNPACK2(gg0, go0, acc[r][1]);
        UNPACK2(gi1, gf1, acc[r][2]); UNPACK2(gg1, go1, acc[r][3]);
        gi0 += bb[0]; gf0 += bb[1]; gg0 += bb[2]; go0 += bb[3];
        gi1 += bb[4]; gf1 += bb[5]; gg1 += bb[6]; go1 += bb[7];
        {
            float cold = cbuf[m*HID + u0];
            float cn = sigm_f(gf0)*cold + sigm_f(gi0)*tanh_f(gg0);
            cbuf[m*HID + u0] = cn;
            hout[m*HID + u0] = sigm_f(go0)*tanh_f(cn);
        }
        {
            float cold = cbuf[m*HID + u0 + 1];
            float cn = sigm_f(gf1)*cold + sigm_f(gi1)*tanh_f(gg1);
            cbuf[m*HID + u0 + 1] = cn;
            hout[m*HID + u0 + 1] = sigm_f(go1)*tanh_f(cn);
        }
    }
}

// ---------------- fc head: pred = h1 @ Wfc^T + b ; feeds BG back ----------------
__global__ void fc_kernel(const float* __restrict__ h1, const float* __restrict__ Wfc,
                          const float* __restrict__ bfc, float* __restrict__ out,
                          float* __restrict__ pred, int tstep)
{
    int gtid = blockIdx.x*blockDim.x + threadIdx.x;
    int row  = gtid >> 5;
    int lane = gtid & 31;
    if (row >= BATCH) return;
    const float* hr = h1 + row*HID;
    float s = 0.f;
    #pragma unroll
    for (int k = lane; k < HID; k += 32) s += hr[k]*Wfc[k];
    #pragma unroll
    for (int o = 16; o > 0; o >>= 1) s += __shfl_xor_sync(0xffffffffu, s, o);
    if (lane == 0) {
        float p = s + bfc[0];
        out[row*HORIZON + tstep] = p;
        pred[row] = p;
    }
}

// ---------------- launch ----------------
extern "C" void kernel_launch(void* const* d_in, const int* in_sizes, int n_in,
                              void* d_out, int out_size)
{
    const float* inputs = (const float*)d_in[0];
    const float* Wih0 = (const float*)d_in[1];
    const float* Whh0 = (const float*)d_in[2];
    const float* bih0 = (const float*)d_in[3];
    const float* bhh0 = (const float*)d_in[4];
    const float* Wih1 = (const float*)d_in[5];
    const float* Whh1 = (const float*)d_in[6];
    const float* bih1 = (const float*)d_in[7];
    const float* bhh1 = (const float*)d_in[8];
    const float* Wfc  = (const float*)d_in[9];
    const float* bfc  = (const float*)d_in[10];
    float* out = (float*)d_out;

    float *pWx0,*pWh0,*pb0,*pWx1,*pWh1,*pb1,*ph0,*ph1,*pc0,*pc1,*ppred;
    cudaGetSymbolAddress((void**)&pWx0, g_Wx0);
    cudaGetSymbolAddress((void**)&pWh0, g_Wh0);
    cudaGetSymbolAddress((void**)&pb0 , g_b0 );
    cudaGetSymbolAddress((void**)&pWx1, g_Wx1);
    cudaGetSymbolAddress((void**)&pWh1, g_Wh1);
    cudaGetSymbolAddress((void**)&pb1 , g_b1 );
    cudaGetSymbolAddress((void**)&ph0 , g_h0 );
    cudaGetSymbolAddress((void**)&ph1 , g_h1 );
    cudaGetSymbolAddress((void**)&pc0 , g_c0 );
    cudaGetSymbolAddress((void**)&pc1 , g_c1 );
    cudaGetSymbolAddress((void**)&ppred, g_pred);

    prep_kernel<<<4096, 256>>>(Wih0, Whh0, bih0, bhh0, Wih1, Whh1, bih1, bhh1);

    dim3 grid(BATCH/128, GATES/128);
    for (int t = 0; t < TSTEPS; t++) {
        int rp = t & 1;          // read (prev h) buffer
        int wp = 1 - rp;         // write (new h) buffer
        int use_bg = (t > LOOKBACK) ? 1 : 0;
        // layer 0: x from inputs (BG slot overridden with fed-back pred in decode)
        lstm_cell<<<grid, 256>>>(inputs + t*DIN, TSTEPS*DIN, DIN,
                                 pWx0, pWh0, pb0,
                                 ph0 + rp*STATE, pc0, ph0 + wp*STATE,
                                 use_bg ? ppred : (const float*)nullptr, use_bg);
        // layer 1: x = layer0's fresh h
        lstm_cell<<<grid, 256>>>(ph0 + wp*STATE, HID, HID,
                                 pWx1, pWh1, pb1,
                                 ph1 + rp*STATE, pc1, ph1 + wp*STATE,
                                 (const float*)nullptr, 0);
        if (t >= LOOKBACK)
            fc_kernel<<<BATCH/8, 256>>>(ph1 + wp*STATE, Wfc, bfc, out, ppred,
                                        t - LOOKBACK);
    }
}

// round 4
// speedup vs baseline: 2.7079x; 2.7079x over previous
#include <cuda_runtime.h>
#include <cstdint>

#define BATCH    8192
#define HID      128
#define GATES    512
#define LOOKBACK 48
#define HORIZON  12
#define TSTEPS   60
#define DIN      8
#define STATE    (BATCH*HID)
#define KROW0    160          // 8 x-cols + 24 zero pad + 128 h-cols
#define KROW1    256

// ---- device globals (no allocation allowed) ----
__device__ float g_WB0[KROW0*GATES];   // k-major [k][n], n = unit*4+gate
__device__ float g_WB1[KROW1*GATES];
__device__ float g_b0 [GATES];
__device__ float g_b1 [GATES];
__device__ float g_h0 [2*STATE];
__device__ float g_h1 [2*STATE];
__device__ float g_c0 [STATE];
__device__ float g_c1 [STATE];
__device__ float g_pred[BATCH];

// ---- smem layout (bytes, dynamic) ----
// bias: [0,1024). A bufs: 128x36 f32 each. B bufs: 32x264 f32 each.
// epilogue cbuf/hbuf (128x65 f32 each) alias the A/B region (dead by then).
#define SM_AS(b)  (1024 + (b)*18432)
#define SM_BS(b)  (1024 + 36864 + (b)*33792)
#define SM_CB     1024
#define SM_HB     (1024 + 33280)
#define SMEM_TOTAL 105472

// ---------------- helpers ----------------
__device__ __forceinline__ float rna_tf32(float x){
    uint32_t u; asm("cvt.rna.tf32.f32 %0, %1;" : "=r"(u) : "f"(x));
    return __uint_as_float(u);
}
__device__ __forceinline__ uint32_t smem_u32(const void* p){
    uint32_t a;
    asm("{ .reg .u64 t; cvta.to.shared.u64 t, %1; cvt.u32.u64 %0, t; }" : "=r"(a) : "l"(p));
    return a;
}
__device__ __forceinline__ void cpa16(uint32_t dst, const void* src){
    asm volatile("cp.async.cg.shared.global [%0], [%1], 16;" :: "r"(dst), "l"(src));
}
__device__ __forceinline__ void mma8(float* d, const uint32_t* a, const uint32_t* b){
    asm volatile("mma.sync.aligned.m16n8k8.row.col.f32.tf32.tf32.f32 "
        "{%0,%1,%2,%3}, {%4,%5,%6,%7}, {%8,%9}, {%0,%1,%2,%3};"
        : "+f"(d[0]), "+f"(d[1]), "+f"(d[2]), "+f"(d[3])
        : "r"(a[0]), "r"(a[1]), "r"(a[2]), "r"(a[3]), "r"(b[0]), "r"(b[1]));
}
__device__ __forceinline__ float sigm_f(float x){
    x = fminf(fmaxf(x, -30.f), 30.f);
    return __fdividef(1.f, 1.f + __expf(-x));
}
__device__ __forceinline__ float tanh_f(float x){
    x = fminf(fmaxf(x, -15.f), 15.f);
    float e = __expf(2.f*x);
    return 1.f - __fdividef(2.f, e + 1.f);
}

// ---------------- weight repack (k-major, tf32-rounded) + state zero ----------------
__global__ void prep_kernel(const float* __restrict__ Wih0, const float* __restrict__ Whh0,
                            const float* __restrict__ bih0, const float* __restrict__ bhh0,
                            const float* __restrict__ Wih1, const float* __restrict__ Whh1,
                            const float* __restrict__ bih1, const float* __restrict__ bhh1)
{
    const int NW0 = KROW0*GATES, NW1 = KROW1*GATES;
    const int total = NW0 + NW1 + 2*GATES + 4*STATE;
    for (int idx = blockIdx.x*blockDim.x + threadIdx.x; idx < total;
         idx += gridDim.x*blockDim.x) {
        int i = idx;
        if (i < NW0) { int k = i>>9, n = i&511; int row = (n&3)*HID + (n>>2);
            float v = 0.f;
            if (k < DIN)       v = Wih0[row*DIN + k];
            else if (k >= 32)  v = Whh0[row*HID + (k-32)];
            g_WB0[i] = rna_tf32(v); continue; }
        i -= NW0;
        if (i < NW1) { int k = i>>9, n = i&511; int row = (n&3)*HID + (n>>2);
            float v = (k < HID) ? Wih1[row*HID + k] : Whh1[row*HID + (k-HID)];
            g_WB1[i] = rna_tf32(v); continue; }
        i -= NW1;
        if (i < GATES) { int row = (i&3)*HID + (i>>2); g_b0[i] = bih0[row]+bhh0[row]; continue; }
        i -= GATES;
        if (i < GATES) { int row = (i&3)*HID + (i>>2); g_b1[i] = bih1[row]+bhh1[row]; continue; }
        i -= GATES;
        if (i < STATE) { g_h0[i] = 0.f; continue; }
        i -= STATE;
        if (i < STATE) { g_h1[i] = 0.f; continue; }
        i -= STATE;
        if (i < STATE) { g_c0[i] = 0.f; continue; }
        i -= STATE;
        g_c1[i] = 0.f;
    }
}

// ---------------- fused LSTM cell: tf32 mma.sync, M=128 x N=256 CTA tile ----------------
__global__ __launch_bounds__(256, 1) void lstm_cell_mma(
    const float* __restrict__ xsrc, int sx, int Kx,
    const float* __restrict__ bg,
    const float* __restrict__ hprev,
    const float* __restrict__ WB, int Krow,
    const float* __restrict__ bias,
    float* __restrict__ cglob, float* __restrict__ hout)
{
    extern __shared__ __align__(16) char smem[];
    const int tid = threadIdx.x, lane = tid & 31, wid = tid >> 5;
    const int m0 = blockIdx.x * 128, n0 = blockIdx.y * 256;
    const int wm0 = (wid >> 2) * 64, wn0 = (wid & 3) * 64;
    const int r = lane >> 2, cq = lane & 3;
    const uint32_t sbase = smem_u32(smem);

    ((float*)smem)[tid] = bias[n0 + tid];

    float acc[4][8][4];
    #pragma unroll
    for (int a = 0; a < 4; a++)
        #pragma unroll
        for (int b = 0; b < 8; b++)
            #pragma unroll
            for (int d = 0; d < 4; d++) acc[a][b][d] = 0.f;

    const int nch = Krow >> 5;

    // -------- chunk issue (cp.async) --------
    auto issue = [&](int j){
        const int b = j & 1;
        const uint32_t asb = sbase + SM_AS(b);
        const uint32_t bsb = sbase + SM_BS(b);
        const float* wsrc = WB + (size_t)(j*32)*GATES + n0;
        #pragma unroll
        for (int i = 0; i < 8; i++) {          // B: 32 k-rows x 256 n
            int idx = tid + i*256;
            int kk = idx >> 6, q = idx & 63;
            cpa16(bsb + (uint32_t)(kk*264 + q*4)*4, wsrc + (size_t)kk*GATES + q*4);
        }
        if (!(Kx == DIN && j == 0)) {          // A: 128 m x 32 k
            const float* ap; int koff, ss;
            if (Kx == DIN)      { ap = hprev; ss = HID; koff = (j-1)*32; }
            else if (j < 4)     { ap = xsrc;  ss = sx;  koff = j*32; }
            else                { ap = hprev; ss = HID; koff = (j-4)*32; }
            #pragma unroll
            for (int i = 0; i < 4; i++) {
                int idx = tid + i*256;
                int m = idx >> 3, q = idx & 7;
                cpa16(asb + (uint32_t)(m*36 + q*4)*4, ap + (size_t)(m0+m)*ss + koff + q*4);
            }
        }
    };

    // layer-0 chunk 0: x cols (tf32-cvt + BG feedback) + zero pad, manual STS
    if (Kx == DIN) {
        float* As0 = (float*)(smem + SM_AS(0));
        int m = tid >> 1, hh = tid & 1;
        #pragma unroll
        for (int cc = 0; cc < 16; cc++) {
            int k = hh*16 + cc;
            float v = 0.f;
            if (k < DIN) {
                v = (bg && k == 0) ? bg[m0+m] : xsrc[(size_t)(m0+m)*sx + k];
                v = rna_tf32(v);
            }
            As0[m*36 + k] = v;
        }
    }
    issue(0);
    asm volatile("cp.async.commit_group;" ::: "memory");

    // -------- mainloop --------
    for (int j = 0; j < nch; j++) {
        const int b = j & 1;
        if (j + 1 < nch) {
            issue(j + 1);
            asm volatile("cp.async.commit_group;" ::: "memory");
            asm volatile("cp.async.wait_group 1;" ::: "memory");
        } else {
            asm volatile("cp.async.wait_group 0;" ::: "memory");
        }
        __syncthreads();
        const uint32_t* As = (const uint32_t*)(smem + SM_AS(b));
        const uint32_t* Bs = (const uint32_t*)(smem + SM_BS(b));
        #pragma unroll
        for (int s = 0; s < 4; s++) {
            uint32_t af[4][4];
            #pragma unroll
            for (int mi = 0; mi < 4; mi++) {
                int row0 = wm0 + mi*16 + r;
                af[mi][0] = As[ row0   *36 + s*8 + cq];
                af[mi][1] = As[(row0+8)*36 + s*8 + cq];
                af[mi][2] = As[ row0   *36 + s*8 + cq + 4];
                af[mi][3] = As[(row0+8)*36 + s*8 + cq + 4];
            }
            uint32_t bf[8][2];
            #pragma unroll
            for (int nj = 0; nj < 8; nj++) {
                int colb = wn0 + nj*8 + r;
                bf[nj][0] = Bs[(s*8     + cq)*264 + colb];
                bf[nj][1] = Bs[(s*8 + 4 + cq)*264 + colb];
            }
            #pragma unroll
            for (int mi = 0; mi < 4; mi++)
                #pragma unroll
                for (int nj = 0; nj < 8; nj++)
                    mma8(acc[mi][nj], af[mi], bf[nj]);
        }
        __syncthreads();
    }

    // -------- epilogue --------
    float* cbuf = (float*)(smem + SM_CB);
    float* hbuf = (float*)(smem + SM_HB);
    const int ub = n0 >> 2;            // unit base (global) for this CTA
    #pragma unroll
    for (int i = 0; i < 8; i++) {      // cold: global -> smem, coalesced
        int idx = tid + i*256;
        int m = idx >> 4, q = idx & 15;
        float4 v = *(const float4*)&cglob[(size_t)(m0+m)*HID + ub + q*4];
        cbuf[m*65 + q*4 + 0] = v.x; cbuf[m*65 + q*4 + 1] = v.y;
        cbuf[m*65 + q*4 + 2] = v.z; cbuf[m*65 + q*4 + 3] = v.w;
    }
    __syncthreads();
    const float* bsm = (const float*)smem;
    #pragma unroll
    for (int mi = 0; mi < 4; mi++) {
        #pragma unroll
        for (int nj = 0; nj < 8; nj++) {
            int nl = wn0 + nj*8 + 2*cq;
            float v0 = acc[mi][nj][0] + bsm[nl];
            float v1 = acc[mi][nj][1] + bsm[nl+1];
            float v2 = acc[mi][nj][2] + bsm[nl];
            float v3 = acc[mi][nj][3] + bsm[nl+1];
            float p0 = __shfl_xor_sync(0xffffffffu, v0, 1);
            float p1 = __shfl_xor_sync(0xffffffffu, v1, 1);
            float p2 = __shfl_xor_sync(0xffffffffu, v2, 1);
            float p3 = __shfl_xor_sync(0xffffffffu, v3, 1);
            if (!(lane & 1)) {         // even lanes hold (i,f); partner held (g,o)
                int u  = (wn0 + nj*8 + 2*cq) >> 2;
                int ml = wm0 + mi*16 + r;
                {
                    float cold = cbuf[ml*65 + u];
                    float cn = sigm_f(v1)*cold + sigm_f(v0)*tanh_f(p0);
                    cbuf[ml*65 + u] = cn;
                    hbuf[ml*65 + u] = rna_tf32(sigm_f(p1)*tanh_f(cn));
                }
                {
                    float cold = cbuf[(ml+8)*65 + u];
                    float cn = sigm_f(v3)*cold + sigm_f(v2)*tanh_f(p2);
                    cbuf[(ml+8)*65 + u] = cn;
                    hbuf[(ml+8)*65 + u] = rna_tf32(sigm_f(p3)*tanh_f(cn));
                }
            }
        }
    }
    __syncthreads();
    #pragma unroll
    for (int i = 0; i < 8; i++) {      // writeback, coalesced
        int idx = tid + i*256;
        int m = idx >> 4, q = idx & 15;
        float4 cv, hv;
        cv.x = cbuf[m*65 + q*4 + 0]; cv.y = cbuf[m*65 + q*4 + 1];
        cv.z = cbuf[m*65 + q*4 + 2]; cv.w = cbuf[m*65 + q*4 + 3];
        hv.x = hbuf[m*65 + q*4 + 0]; hv.y = hbuf[m*65 + q*4 + 1];
        hv.z = hbuf[m*65 + q*4 + 2]; hv.w = hbuf[m*65 + q*4 + 3];
        *(float4*)&cglob[(size_t)(m0+m)*HID + ub + q*4] = cv;
        *(float4*)&hout [(size_t)(m0+m)*HID + ub + q*4] = hv;
    }
}

// ---------------- fc head ----------------
__global__ void fc_kernel(const float* __restrict__ h1, const float* __restrict__ Wfc,
                          const float* __restrict__ bfc, float* __restrict__ out,
                          float* __restrict__ pred, int tstep)
{
    int gtid = blockIdx.x*blockDim.x + threadIdx.x;
    int row  = gtid >> 5;
    int lane = gtid & 31;
    if (row >= BATCH) return;
    const float* hr = h1 + (size_t)row*HID;
    float s = 0.f;
    #pragma unroll
    for (int k = lane; k < HID; k += 32) s += hr[k]*Wfc[k];
    #pragma unroll
    for (int o = 16; o > 0; o >>= 1) s += __shfl_xor_sync(0xffffffffu, s, o);
    if (lane == 0) {
        float p = s + bfc[0];
        out[row*HORIZON + tstep] = p;
        pred[row] = p;
    }
}

// ---------------- launch ----------------
extern "C" void kernel_launch(void* const* d_in, const int* in_sizes, int n_in,
                              void* d_out, int out_size)
{
    const float* inputs = (const float*)d_in[0];
    const float* Wih0 = (const float*)d_in[1];
    const float* Whh0 = (const float*)d_in[2];
    const float* bih0 = (const float*)d_in[3];
    const float* bhh0 = (const float*)d_in[4];
    const float* Wih1 = (const float*)d_in[5];
    const float* Whh1 = (const float*)d_in[6];
    const float* bih1 = (const float*)d_in[7];
    const float* bhh1 = (const float*)d_in[8];
    const float* Wfc  = (const float*)d_in[9];
    const float* bfc  = (const float*)d_in[10];
    float* out = (float*)d_out;

    float *pWB0,*pWB1,*pb0,*pb1,*ph0,*ph1,*pc0,*pc1,*ppred;
    cudaGetSymbolAddress((void**)&pWB0, g_WB0);
    cudaGetSymbolAddress((void**)&pWB1, g_WB1);
    cudaGetSymbolAddress((void**)&pb0 , g_b0 );
    cudaGetSymbolAddress((void**)&pb1 , g_b1 );
    cudaGetSymbolAddress((void**)&ph0 , g_h0 );
    cudaGetSymbolAddress((void**)&ph1 , g_h1 );
    cudaGetSymbolAddress((void**)&pc0 , g_c0 );
    cudaGetSymbolAddress((void**)&pc1 , g_c1 );
    cudaGetSymbolAddress((void**)&ppred, g_pred);

    cudaFuncSetAttribute(lstm_cell_mma, cudaFuncAttributeMaxDynamicSharedMemorySize, SMEM_TOTAL);

    prep_kernel<<<2048, 256>>>(Wih0, Whh0, bih0, bhh0, Wih1, Whh1, bih1, bhh1);

    dim3 grid(BATCH/128, GATES/256);
    for (int t = 0; t < TSTEPS; t++) {
        int rp = t & 1;
        int wp = 1 - rp;
        int use_bg = (t > LOOKBACK) ? 1 : 0;
        lstm_cell_mma<<<grid, 256, SMEM_TOTAL>>>(
            inputs + t*DIN, TSTEPS*DIN, DIN,
            use_bg ? ppred : (const float*)nullptr,
            ph0 + rp*STATE, pWB0, KROW0, pb0,
            pc0, ph0 + wp*STATE);
        lstm_cell_mma<<<grid, 256, SMEM_TOTAL>>>(
            ph0 + wp*STATE, HID, HID,
            (const float*)nullptr,
            ph1 + rp*STATE, pWB1, KROW1, pb1,
            pc1, ph1 + wp*STATE);
        if (t >= LOOKBACK)
            fc_kernel<<<BATCH/8, 256>>>(ph1 + wp*STATE, Wfc, bfc, out, ppred,
                                        t - LOOKBACK);
    }
}